// round 14
// baseline (speedup 1.0000x reference)
#include <cuda_runtime.h>
#include <cuda_bf16.h>

#define NB     32
#define NZ     100
#define STATE  20
#define HIDN   128
#define HH     32
#define WW     32
#define STEPS  64
#define THRESH 0.1f

#define PIX    1024
#define IMG_SZ (STATE*PIX)
#define STATE_SZ (NB*IMG_SZ)
#define SPR    4
#define NSTRIP 128
#define TOTSTRIP 4096

// ---------------- persistent device scratch (ping-pong) ----------------
__device__ __align__(16) float g_T[2*STATE_SZ];
__device__ unsigned char      g_PM[2*TOTSTRIP];   // per-strip pre-mask byte
__device__ unsigned char      g_HT[2*TOTSTRIP];   // per-strip "T computed this step"
// packed weights (R1 layout)
__device__ __align__(16) float g_wp_pad [60*128*4];   // [cr][h][4] (kx 0..2)
__device__ __align__(16) float g_wu1_pad[32*128*4];   // [kg][h][4]

__device__ __forceinline__ void group_bar(int g) {
    asm volatile("bar.sync %0, 128;" :: "r"(g + 1) : "memory");
}

// ---------------- weight repack ----------------
__global__ void k_pack(const float* __restrict__ wp, const float* __restrict__ wu1)
{
    int i = blockIdx.x*256 + threadIdx.x;
    if (i < 128*180) {
        int h = i / 180, k = i % 180;            // k = c*9 + r*3 + kx
        g_wp_pad[(k/3)*512 + h*4 + (k%3)] = wp[i];
    }
    if (i < 128*128) {
        int h = i / 128, k = i % 128;
        g_wu1_pad[(k>>2)*512 + h*4 + (k&3)] = wu1[i];
    }
}

// ---------------- zero T buf0 + all flags ----------------
__global__ void k_zero()
{
    int i = blockIdx.x*256 + threadIdx.x;
    if (i < STATE_SZ) g_T[i] = 0.f;
    if (i < 2*TOTSTRIP) { g_PM[i] = 0; g_HT[i] = 0; }
}

// ---------------- init MLP: z -> center pixel of T buf0 ----------------
__global__ void k_init(const float* __restrict__ z,
                       const float* __restrict__ w1, const float* __restrict__ b1,
                       const float* __restrict__ w2, const float* __restrict__ b2)
{
    int n = blockIdx.x;
    int t = threadIdx.x;  // 128 threads
    __shared__ float zz[NZ];
    __shared__ float h[50];
    if (t < NZ) zz[t] = z[n*NZ + t];
    __syncthreads();
    if (t < 50) {
        float a = b1[t];
        #pragma unroll 4
        for (int j = 0; j < NZ; j++) a += w1[t*NZ + j] * zz[j];
        h[t] = fmaxf(a, 0.f);
    }
    __syncthreads();
    const int ctr = 16*WW + 16;
    if (t < STATE-1) {
        float a = b2[t];
        #pragma unroll 5
        for (int j = 0; j < 50; j++) a += w2[t*50 + j] * h[j];
        g_T[n*IMG_SZ + (1+t)*PIX + ctr] = a;
    }
    if (t == STATE-1) {
        g_T[n*IMG_SZ + ctr] = 0.5f;
        g_PM[n*NSTRIP + 16*SPR + 2] = 0x01;      // center strip, pixel 0 (=col 16)
        g_HT[n*NSTRIP + 16*SPR + 2] = 1;
    }
}

// ---------------- fused step kernel: CTA = one row (4 strips, 4 groups) ----------------
// grid (32, 32) = (row y, image n); block 512 = 4 groups x 128
__global__ void __launch_bounds__(512)
k_step(int step,
       const float* __restrict__ bp,
       const float* __restrict__ bu1,
       const float* __restrict__ wu2, const float* __restrict__ bu2)
{
    __shared__ __align__(16) float patch[4][STATE][3][12];
    __shared__ __align__(16) float s_perc[4][HIDN][8];
    __shared__ __align__(16) float s_h2 [4][HIDN][8];
    __shared__ __align__(16) float tch0[4][5][12];
    __shared__ unsigned char s_pm[4][16], s_hot[4][16];
    __shared__ unsigned char aflag[4][3][10];
    __shared__ int sflag[4];

    const int in = step & 1;
    const float* __restrict__ Tin  = g_T + in*STATE_SZ;
    float*       __restrict__ Tout = g_T + (in^1)*STATE_SZ;
    const unsigned char* __restrict__ PMin  = g_PM + in*TOTSTRIP;
    unsigned char*       __restrict__ PMout = g_PM + (in^1)*TOTSTRIP;
    const unsigned char* __restrict__ HTin  = g_HT + in*TOTSTRIP;
    unsigned char*       __restrict__ HTout = g_HT + (in^1)*TOTSTRIP;

    const int y  = blockIdx.x;
    const int n  = blockIdx.y;
    const int t  = threadIdx.x;
    const int g  = t >> 7;               // group = strip column
    const int tl = t & 127;
    const int sx = g;
    const int x0 = sx * 8;
    const int se = n*NSTRIP + y*SPR + sx;
    const int first = (step == 0);

    // ---- gate: any pre pixel in rows y-2..y+2, cols x0-2..x0+9 ----
    if (tl < 32) {
        int h1 = 0;
        if (tl < 15) {
            int dy = tl/3 - 2, ds = tl%3 - 1;
            int yy = y + dy, ss = sx + ds;
            unsigned pm = 0, ht = 0;
            if ((unsigned)yy < (unsigned)HH && (unsigned)ss < (unsigned)SPR) {
                pm = PMin[n*NSTRIP + yy*SPR + ss];
                ht = HTin[n*NSTRIP + yy*SPR + ss];
            }
            s_pm[g][tl]  = (unsigned char)pm;
            s_hot[g][tl] = (unsigned char)ht;
            unsigned cm = (ds == 0) ? 0xFFu : (ds < 0 ? 0xC0u : 0x03u);
            h1 = (pm & cm) != 0;
        }
        h1 = __any_sync(0xffffffffu, h1);
        if (tl == 0) {
            sflag[g] = h1;
            HTout[se] = (unsigned char)h1;
            if (!h1) PMout[se] = 0;
        }
    }
    group_bar(g);
    if (!sflag[g]) return;

    // ---- stage T_in ch0 5x12, gated by HOT_in ----
    if (tl < 60) {
        int rr = tl / 12, cc = tl % 12;
        int yy = y - 2 + rr, xx = x0 - 2 + cc;
        float v = 0.f;
        if ((unsigned)yy < (unsigned)HH && (unsigned)xx < (unsigned)WW) {
            int hidx = rr*3 + ((xx >> 3) - sx + 1);
            if (s_hot[g][hidx]) v = Tin[n*IMG_SZ + yy*WW + xx];
        }
        tch0[g][rr][cc] = v;
    }
    group_bar(g);

    // ---- alive flags for 3x10 halo ----
    if (tl < 30) {
        int r = tl / 10, col = tl % 10;
        int yy = y - 1 + r, xx = x0 - 1 + col;
        int f = 0;
        if ((unsigned)yy < (unsigned)HH && (unsigned)xx < (unsigned)WW) {
            int pidx = (r + 1)*3 + ((xx >> 3) - sx + 1);
            if ((s_pm[g][pidx] >> (xx & 7)) & 1) {
                if (first) f = 1;
                else {
                    float m = -1.f;
                    #pragma unroll
                    for (int dr = 0; dr < 3; dr++)
                        #pragma unroll
                        for (int dc = 0; dc < 3; dc++)
                            m = fmaxf(m, tch0[g][r + dr][col + dc]);
                    f = (m > THRESH) ? 1 : 0;
                }
            }
        }
        aflag[g][r][col] = (unsigned char)f;
    }
    group_bar(g);

    // ---- build patch = masked S over [20][3][12] ----
    for (int i = tl; i < STATE*3*12; i += 128) {
        int c = i / 36, rem = i - c*36, r = rem / 12, col = rem - r*12;
        float v = 0.f;
        if (col < 10 && aflag[g][r][col]) {
            int yy = y - 1 + r, xx = x0 - 1 + col;
            v = Tin[n*IMG_SZ + c*PIX + yy*WW + xx];
        }
        patch[g][c][r][col] = v;
    }
    group_bar(g);

    // ---- pre-mask for own 8 pixels -> PM_out byte ----
    if (tl < 32) {
        int pre = 0;
        if (tl < 8) {
            float m = 0.f;
            #pragma unroll
            for (int r = 0; r < 3; r++)
                #pragma unroll
                for (int cc = 0; cc < 3; cc++)
                    m = fmaxf(m, patch[g][0][r][tl + cc]);
            pre = (m > THRESH) ? 1 : 0;
        }
        unsigned bal = __ballot_sync(0xffffffffu, pre);
        if (tl == 0) PMout[se] = (unsigned char)(bal & 0xFF);
    }

    // ---- perceive: 3x3 conv 20->128 ----
    float acc[8];
    {
        float b = bp[tl];
        #pragma unroll
        for (int p = 0; p < 8; p++) acc[p] = b;
    }
    #pragma unroll 2
    for (int c = 0; c < STATE; c++) {
        #pragma unroll
        for (int r = 0; r < 3; r++) {
            const float4 a = *(const float4*)&patch[g][c][r][0];
            const float4 b = *(const float4*)&patch[g][c][r][4];
            const float4 d = *(const float4*)&patch[g][c][r][8];
            float rv[12] = {a.x,a.y,a.z,a.w, b.x,b.y,b.z,b.w, d.x,d.y,d.z,d.w};
            const float4 w4 = *(const float4*)&g_wp_pad[(c*3 + r)*512 + tl*4];
            float wk[3] = {w4.x, w4.y, w4.z};
            #pragma unroll
            for (int kx = 0; kx < 3; kx++)
                #pragma unroll
                for (int p = 0; p < 8; p++)
                    acc[p] = fmaf(wk[kx], rv[p + kx], acc[p]);
        }
    }
    #pragma unroll
    for (int p = 0; p < 8; p++) s_perc[g][tl][p] = acc[p];
    group_bar(g);

    // ---- up1: 1x1 128->128 + ReLU ----
    float acc2[8];
    {
        float b = bu1[tl];
        #pragma unroll
        for (int p = 0; p < 8; p++) acc2[p] = b;
    }
    #pragma unroll 4
    for (int kg = 0; kg < 32; kg++) {
        const float4 w4 = *(const float4*)&g_wu1_pad[kg*512 + tl*4];
        float wk[4] = {w4.x, w4.y, w4.z, w4.w};
        #pragma unroll
        for (int j = 0; j < 4; j++) {
            int k = kg*4 + j;
            const float4 va = *(const float4*)&s_perc[g][k][0];
            const float4 vb = *(const float4*)&s_perc[g][k][4];
            acc2[0] = fmaf(wk[j], va.x, acc2[0]);
            acc2[1] = fmaf(wk[j], va.y, acc2[1]);
            acc2[2] = fmaf(wk[j], va.z, acc2[2]);
            acc2[3] = fmaf(wk[j], va.w, acc2[3]);
            acc2[4] = fmaf(wk[j], vb.x, acc2[4]);
            acc2[5] = fmaf(wk[j], vb.y, acc2[5]);
            acc2[6] = fmaf(wk[j], vb.z, acc2[6]);
            acc2[7] = fmaf(wk[j], vb.w, acc2[7]);
        }
    }
    #pragma unroll
    for (int p = 0; p < 8; p++) s_h2[g][tl][p] = fmaxf(acc2[p], 0.f);
    group_bar(g);

    // ---- up2: 1x1 128->20, T_out = maskedS + upd ----
    {
        int c = tl >> 3, p = tl & 7;
        float a = bu2[c];
        #pragma unroll 8
        for (int k4 = 0; k4 < 32; k4++) {
            const float4 w4 = *(const float4*)&wu2[c*128 + k4*4];
            a = fmaf(w4.x, s_h2[g][k4*4+0][p], a);
            a = fmaf(w4.y, s_h2[g][k4*4+1][p], a);
            a = fmaf(w4.z, s_h2[g][k4*4+2][p], a);
            a = fmaf(w4.w, s_h2[g][k4*4+3][p], a);
        }
        Tout[n*IMG_SZ + c*PIX + y*WW + x0 + p] = patch[g][c][1][p+1] + a;
    }
    if (tl < 32) {
        int i = tl + 128;
        int c = i >> 3, p = i & 7;
        float a = bu2[c];
        #pragma unroll 8
        for (int k4 = 0; k4 < 32; k4++) {
            const float4 w4 = *(const float4*)&wu2[c*128 + k4*4];
            a = fmaf(w4.x, s_h2[g][k4*4+0][p], a);
            a = fmaf(w4.y, s_h2[g][k4*4+1][p], a);
            a = fmaf(w4.z, s_h2[g][k4*4+2][p], a);
            a = fmaf(w4.w, s_h2[g][k4*4+3][p], a);
        }
        Tout[n*IMG_SZ + c*PIX + y*WW + x0 + p] = patch[g][c][1][p+1] + a;
    }
}

// ---------------- extract: reconstruct masked ch0 (final parity = 0) ----------------
__global__ void k_extract(float* __restrict__ out)
{
    int gg = blockIdx.x*256 + threadIdx.x;     // 0..32767
    int n = gg >> 10, rem = gg & 1023;
    int y = rem >> 5, x = rem & 31;

    float v = 0.f;
    unsigned pm = g_PM[n*NSTRIP + y*SPR + (x >> 3)];
    if ((pm >> (x & 7)) & 1) {
        const float* __restrict__ Tn = g_T + n*IMG_SZ;
        float m = -1.f;
        #pragma unroll
        for (int dy = -1; dy <= 1; dy++) {
            int yy = y + dy;
            if ((unsigned)yy >= (unsigned)HH) continue;
            #pragma unroll
            for (int dx = -1; dx <= 1; dx++) {
                int xx = x + dx;
                if ((unsigned)xx >= (unsigned)WW) continue;
                if (g_HT[n*NSTRIP + yy*SPR + (xx >> 3)])
                    m = fmaxf(m, Tn[yy*WW + xx]);
            }
        }
        if (m > THRESH) v = Tn[rem];
    }
    out[gg] = v;
}

// ---------------- launch ----------------
extern "C" void kernel_launch(void* const* d_in, const int* in_sizes, int n_in,
                              void* d_out, int out_size)
{
    const float* z   = (const float*)d_in[0];
    const float* w1  = (const float*)d_in[1];
    const float* b1  = (const float*)d_in[2];
    const float* w2  = (const float*)d_in[3];
    const float* b2  = (const float*)d_in[4];
    const float* wp  = (const float*)d_in[5];
    const float* bp  = (const float*)d_in[6];
    const float* wu1 = (const float*)d_in[7];
    const float* bu1 = (const float*)d_in[8];
    const float* wu2 = (const float*)d_in[9];
    const float* bu2 = (const float*)d_in[10];
    float* out = (float*)d_out;

    k_pack<<<(128*180 + 255)/256, 256>>>(wp, wu1);
    k_zero<<<(STATE_SZ + 255)/256, 256>>>();
    k_init<<<NB, 128>>>(z, w1, b1, w2, b2);

    for (int s = 0; s < STEPS; s++)
        k_step<<<dim3(32, 32), 512>>>(s, bp, bu1, wu2, bu2);

    k_extract<<<(NB*PIX)/256, 256>>>(out);
}

// round 15
// speedup vs baseline: 1.0474x; 1.0474x over previous
#include <cuda_runtime.h>
#include <cuda_bf16.h>

#define NB     32
#define NZ     100
#define STATE  20
#define HIDN   128
#define HH     32
#define WW     32
#define STEPS  64
#define THRESH 0.1f

#define PIX    1024
#define IMG_SZ (STATE*PIX)
#define STATE_SZ (NB*IMG_SZ)
#define SPR    4
#define NSTRIP 128
#define TOTSTRIP 4096

// ---------------- persistent device scratch (ping-pong) ----------------
__device__ __align__(16) float g_T[2*STATE_SZ];
__device__ unsigned char      g_PM[2*TOTSTRIP];   // per-strip pre-mask byte
__device__ unsigned char      g_HT[2*TOTSTRIP];   // per-strip "T computed this step"
// packed weights (R1 layout)
__device__ __align__(16) float g_wp_pad [60*128*4];   // [cr][h][4] (kx 0..2)
__device__ __align__(16) float g_wu1_pad[32*128*4];   // [kg][h][4]

// ---------------- weight repack ----------------
__global__ void k_pack(const float* __restrict__ wp, const float* __restrict__ wu1)
{
    int i = blockIdx.x*256 + threadIdx.x;
    if (i < 128*180) {
        int h = i / 180, k = i % 180;            // k = c*9 + r*3 + kx
        g_wp_pad[(k/3)*512 + h*4 + (k%3)] = wp[i];
    }
    if (i < 128*128) {
        int h = i / 128, k = i % 128;
        g_wu1_pad[(k>>2)*512 + h*4 + (k&3)] = wu1[i];
    }
}

// ---------------- zero T buf0 + all flags (replay determinism) ----------------
__global__ void k_zero()
{
    int i = blockIdx.x*256 + threadIdx.x;
    if (i < STATE_SZ) g_T[i] = 0.f;
    if (i < 2*TOTSTRIP) { g_PM[i] = 0; g_HT[i] = 0; }
}

// ---------------- init MLP: z -> center pixel of T buf0 ----------------
__global__ void k_init(const float* __restrict__ z,
                       const float* __restrict__ w1, const float* __restrict__ b1,
                       const float* __restrict__ w2, const float* __restrict__ b2)
{
    int n = blockIdx.x;
    int t = threadIdx.x;  // 128 threads
    __shared__ float zz[NZ];
    __shared__ float h[50];
    if (t < NZ) zz[t] = z[n*NZ + t];
    __syncthreads();
    if (t < 50) {
        float a = b1[t];
        #pragma unroll 4
        for (int j = 0; j < NZ; j++) a += w1[t*NZ + j] * zz[j];
        h[t] = fmaxf(a, 0.f);
    }
    __syncthreads();
    const int ctr = 16*WW + 16;
    if (t < STATE-1) {
        float a = b2[t];
        #pragma unroll 5
        for (int j = 0; j < 50; j++) a += w2[t*50 + j] * h[j];
        g_T[n*IMG_SZ + (1+t)*PIX + ctr] = a;
    }
    if (t == STATE-1) {
        g_T[n*IMG_SZ + ctr] = 0.5f;
        g_PM[n*NSTRIP + 16*SPR + 2] = 0x01;      // center strip, pixel 0 (=col 16)
        g_HT[n*NSTRIP + 16*SPR + 2] = 1;
    }
}

// ---------------- fused step kernel (R13 core + bounded grid offsets) ----------------
// grid: (ncols, nrows, 32); strip = (c_lo+bx, y_lo+by); block: 128 threads
__global__ void __launch_bounds__(128)
k_step(int step, int y_lo, int c_lo,
       const float* __restrict__ bp,
       const float* __restrict__ bu1,
       const float* __restrict__ wu2, const float* __restrict__ bu2)
{
    __shared__ __align__(16) float patch[STATE][3][12];
    __shared__ __align__(16) float s_perc[HIDN][8];
    __shared__ __align__(16) float s_h2 [HIDN][8];
    __shared__ __align__(16) float tch0[5][12];
    __shared__ unsigned char s_pm[16], s_hot[16];
    __shared__ unsigned char aflag[3][10];
    __shared__ int sflag;

    const int in = step & 1;
    const float* __restrict__ Tin  = g_T + in*STATE_SZ;
    float*       __restrict__ Tout = g_T + (in^1)*STATE_SZ;
    const unsigned char* __restrict__ PMin  = g_PM + in*TOTSTRIP;
    unsigned char*       __restrict__ PMout = g_PM + (in^1)*TOTSTRIP;
    const unsigned char* __restrict__ HTin  = g_HT + in*TOTSTRIP;
    unsigned char*       __restrict__ HTout = g_HT + (in^1)*TOTSTRIP;

    const int sx = c_lo + blockIdx.x;
    const int x0 = sx * 8;
    const int y  = y_lo + blockIdx.y;
    const int n  = blockIdx.z;
    const int t  = threadIdx.x;
    const int se = n*NSTRIP + y*SPR + sx;
    const int first = (step == 0);

    // ---- gate: any pre pixel in rows y-2..y+2, cols x0-2..x0+9 ----
    if (t < 32) {
        int h1 = 0;
        if (t < 15) {
            int dy = t/3 - 2, ds = t%3 - 1;
            int yy = y + dy, ss = sx + ds;
            unsigned pm = 0, ht = 0;
            if ((unsigned)yy < (unsigned)HH && (unsigned)ss < (unsigned)SPR) {
                pm = PMin[n*NSTRIP + yy*SPR + ss];
                ht = HTin[n*NSTRIP + yy*SPR + ss];
            }
            s_pm[t]  = (unsigned char)pm;
            s_hot[t] = (unsigned char)ht;
            unsigned cm = (ds == 0) ? 0xFFu : (ds < 0 ? 0xC0u : 0x03u);
            h1 = (pm & cm) != 0;
        }
        h1 = __any_sync(0xffffffffu, h1);
        if (t == 0) {
            sflag = h1;
            HTout[se] = (unsigned char)h1;
            if (!h1) PMout[se] = 0;    // cold: kill stale parity flags
        }
    }
    __syncthreads();
    if (!sflag) return;

    // ---- stage T_in ch0 5x12, gated by HOT_in of covering strip ----
    if (t < 60) {
        int rr = t / 12, cc = t % 12;
        int yy = y - 2 + rr, xx = x0 - 2 + cc;
        float v = 0.f;
        if ((unsigned)yy < (unsigned)HH && (unsigned)xx < (unsigned)WW) {
            int hidx = rr*3 + ((xx >> 3) - sx + 1);
            if (s_hot[hidx]) v = Tin[n*IMG_SZ + yy*WW + xx];
        }
        tch0[rr][cc] = v;
    }
    __syncthreads();

    // ---- alive flags for 3x10 halo: PMbit ∧ maxpool3(T ch0) > θ ----
    if (t < 30) {
        int r = t / 10, col = t % 10;
        int yy = y - 1 + r, xx = x0 - 1 + col;
        int f = 0;
        if ((unsigned)yy < (unsigned)HH && (unsigned)xx < (unsigned)WW) {
            int pidx = (r + 1)*3 + ((xx >> 3) - sx + 1);
            if ((s_pm[pidx] >> (xx & 7)) & 1) {
                if (first) f = 1;
                else {
                    float m = -1.f;
                    #pragma unroll
                    for (int dr = 0; dr < 3; dr++)
                        #pragma unroll
                        for (int dc = 0; dc < 3; dc++)
                            m = fmaxf(m, tch0[r + dr][col + dc]);
                    f = (m > THRESH) ? 1 : 0;
                }
            }
        }
        aflag[r][col] = (unsigned char)f;
    }
    __syncthreads();

    // ---- build patch = masked S over [20][3][12] ----
    for (int i = t; i < STATE*3*12; i += 128) {
        int c = i / 36, rem = i - c*36, r = rem / 12, col = rem - r*12;
        float v = 0.f;
        if (col < 10 && aflag[r][col]) {
            int yy = y - 1 + r, xx = x0 - 1 + col;
            v = Tin[n*IMG_SZ + c*PIX + yy*WW + xx];
        }
        patch[c][r][col] = v;
    }
    __syncthreads();

    // ---- pre-mask for own 8 pixels -> PM_out byte ----
    if (t < 32) {
        int pre = 0;
        if (t < 8) {
            float m = 0.f;
            #pragma unroll
            for (int r = 0; r < 3; r++)
                #pragma unroll
                for (int cc = 0; cc < 3; cc++)
                    m = fmaxf(m, patch[0][r][t + cc]);
            pre = (m > THRESH) ? 1 : 0;
        }
        unsigned bal = __ballot_sync(0xffffffffu, pre);
        if (t == 0) PMout[se] = (unsigned char)(bal & 0xFF);
    }

    // ---- perceive: 3x3 conv 20->128 (R1 verbatim) ----
    float acc[8];
    {
        float b = bp[t];
        #pragma unroll
        for (int p = 0; p < 8; p++) acc[p] = b;
    }
    #pragma unroll 2
    for (int c = 0; c < STATE; c++) {
        #pragma unroll
        for (int r = 0; r < 3; r++) {
            const float4 a = *(const float4*)&patch[c][r][0];
            const float4 b = *(const float4*)&patch[c][r][4];
            const float4 d = *(const float4*)&patch[c][r][8];
            float rv[12] = {a.x,a.y,a.z,a.w, b.x,b.y,b.z,b.w, d.x,d.y,d.z,d.w};
            const float4 w4 = *(const float4*)&g_wp_pad[(c*3 + r)*512 + t*4];
            float wk[3] = {w4.x, w4.y, w4.z};
            #pragma unroll
            for (int kx = 0; kx < 3; kx++)
                #pragma unroll
                for (int p = 0; p < 8; p++)
                    acc[p] = fmaf(wk[kx], rv[p + kx], acc[p]);
        }
    }
    #pragma unroll
    for (int p = 0; p < 8; p++) s_perc[t][p] = acc[p];
    __syncthreads();

    // ---- up1: 1x1 128->128 + ReLU (R1 verbatim) ----
    float acc2[8];
    {
        float b = bu1[t];
        #pragma unroll
        for (int p = 0; p < 8; p++) acc2[p] = b;
    }
    #pragma unroll 4
    for (int kg = 0; kg < 32; kg++) {
        const float4 w4 = *(const float4*)&g_wu1_pad[kg*512 + t*4];
        float wk[4] = {w4.x, w4.y, w4.z, w4.w};
        #pragma unroll
        for (int j = 0; j < 4; j++) {
            int k = kg*4 + j;
            const float4 va = *(const float4*)&s_perc[k][0];
            const float4 vb = *(const float4*)&s_perc[k][4];
            acc2[0] = fmaf(wk[j], va.x, acc2[0]);
            acc2[1] = fmaf(wk[j], va.y, acc2[1]);
            acc2[2] = fmaf(wk[j], va.z, acc2[2]);
            acc2[3] = fmaf(wk[j], va.w, acc2[3]);
            acc2[4] = fmaf(wk[j], vb.x, acc2[4]);
            acc2[5] = fmaf(wk[j], vb.y, acc2[5]);
            acc2[6] = fmaf(wk[j], vb.z, acc2[6]);
            acc2[7] = fmaf(wk[j], vb.w, acc2[7]);
        }
    }
    #pragma unroll
    for (int p = 0; p < 8; p++) s_h2[t][p] = fmaxf(acc2[p], 0.f);
    __syncthreads();

    // ---- up2: 1x1 128->20, T_out = maskedS + upd (R1 verbatim) ----
    {
        int c = t >> 3, p = t & 7;
        float a = bu2[c];
        #pragma unroll 8
        for (int k4 = 0; k4 < 32; k4++) {
            const float4 w4 = *(const float4*)&wu2[c*128 + k4*4];
            a = fmaf(w4.x, s_h2[k4*4+0][p], a);
            a = fmaf(w4.y, s_h2[k4*4+1][p], a);
            a = fmaf(w4.z, s_h2[k4*4+2][p], a);
            a = fmaf(w4.w, s_h2[k4*4+3][p], a);
        }
        Tout[n*IMG_SZ + c*PIX + y*WW + x0 + p] = patch[c][1][p+1] + a;
    }
    if (t < 32) {
        int i = t + 128;
        int c = i >> 3, p = i & 7;
        float a = bu2[c];
        #pragma unroll 8
        for (int k4 = 0; k4 < 32; k4++) {
            const float4 w4 = *(const float4*)&wu2[c*128 + k4*4];
            a = fmaf(w4.x, s_h2[k4*4+0][p], a);
            a = fmaf(w4.y, s_h2[k4*4+1][p], a);
            a = fmaf(w4.z, s_h2[k4*4+2][p], a);
            a = fmaf(w4.w, s_h2[k4*4+3][p], a);
        }
        Tout[n*IMG_SZ + c*PIX + y*WW + x0 + p] = patch[c][1][p+1] + a;
    }
}

// ---------------- extract: reconstruct masked ch0 (final parity = 0) ----------------
__global__ void k_extract(float* __restrict__ out)
{
    int gg = blockIdx.x*256 + threadIdx.x;     // 0..32767
    int n = gg >> 10, rem = gg & 1023;
    int y = rem >> 5, x = rem & 31;

    float v = 0.f;
    unsigned pm = g_PM[n*NSTRIP + y*SPR + (x >> 3)];
    if ((pm >> (x & 7)) & 1) {
        const float* __restrict__ Tn = g_T + n*IMG_SZ;
        float m = -1.f;
        #pragma unroll
        for (int dy = -1; dy <= 1; dy++) {
            int yy = y + dy;
            if ((unsigned)yy >= (unsigned)HH) continue;
            #pragma unroll
            for (int dx = -1; dx <= 1; dx++) {
                int xx = x + dx;
                if ((unsigned)xx >= (unsigned)WW) continue;
                if (g_HT[n*NSTRIP + yy*SPR + (xx >> 3)])
                    m = fmaxf(m, Tn[yy*WW + xx]);
            }
        }
        if (m > THRESH) v = Tn[rem];
    }
    out[gg] = v;
}

// ---------------- launch ----------------
extern "C" void kernel_launch(void* const* d_in, const int* in_sizes, int n_in,
                              void* d_out, int out_size)
{
    const float* z   = (const float*)d_in[0];
    const float* w1  = (const float*)d_in[1];
    const float* b1  = (const float*)d_in[2];
    const float* w2  = (const float*)d_in[3];
    const float* b2  = (const float*)d_in[4];
    const float* wp  = (const float*)d_in[5];
    const float* bp  = (const float*)d_in[6];
    const float* wu1 = (const float*)d_in[7];
    const float* bu1 = (const float*)d_in[8];
    const float* wu2 = (const float*)d_in[9];
    const float* bu2 = (const float*)d_in[10];
    float* out = (float*)d_out;

    k_pack<<<(128*180 + 255)/256, 256>>>(wp, wu1);
    k_zero<<<(STATE_SZ + 255)/256, 256>>>();
    k_init<<<NB, 128>>>(z, w1, b1, w2, b2);

    for (int s = 0; s < STEPS; s++) {
        // Provable hot bound: PM support at step s ⊆ B∞(center=16, s).
        // Strip (y,sx) can be hot only if [y-2,y+2]x[8sx-2,8sx+9] hits that box.
        // +1 safety margin on the radius.
        int R = s + 1;                               // bound radius + margin
        int y_lo = 16 - R - 2; if (y_lo < 0) y_lo = 0;
        int y_hi = 16 + R + 2; if (y_hi > 31) y_hi = 31;
        int nrows = y_hi - y_lo + 1;
        // col c valid iff 8c-2 <= 16+R and 8c+9 >= 16-R
        int c_lo = 0;
        while (c_lo < 3 && 8*c_lo + 9 < 16 - R) c_lo++;
        int c_hi = 3;
        while (c_hi > 0 && 8*c_hi - 2 > 16 + R) c_hi--;
        int ncols = c_hi - c_lo + 1;
        k_step<<<dim3(ncols, nrows, NB), 128>>>(s, y_lo, c_lo, bp, bu1, wu2, bu2);
    }
    k_extract<<<(NB*PIX)/256, 256>>>(out);
}